// round 9
// baseline (speedup 1.0000x reference)
#include <cuda_runtime.h>

// Problem constants (from reference): B=16, K=64, H=96, W=96
#define NB 16
#define NK 64
#define NH 96
#define NW 96
#define HW (NH * NW)            // 9216
#define NBK (NB * NK)           // 1024
#define THREADS 256
#define NV4 (HW / 4)            // 2304 float4 per map
#define PER_T (NV4 / THREADS)   // 9 float4 per thread

// Output segment offsets (floats), harness order:
// Dk, tf_Dk, keypoint, tf_keypoint, get_zeta, tf_get_zeta
#define OFF_D 0
#define SZ_D (NB * NK * HW)               // 9437184
#define OFF_KP (2 * SZ_D)                 // 18874368
#define SZ_KP (NB * 3 * NK * 2)           // 6144
#define OFF_Z (OFF_KP + 2 * SZ_KP)        // 18886656
#define SZ_Z (NB * NK)                    // 1024

__device__ __forceinline__ float sigm(float x) {
    return 1.0f / (1.0f + expf(-x));
}

__global__ __launch_bounds__(THREADS) void decode_kernel(
    const float* __restrict__ Rk,
    const float* __restrict__ tfRk,
    float* __restrict__ out)
{
    const int stack = blockIdx.y;            // 0 = Rk, 1 = tf_Rk
    const int bk    = blockIdx.x;            // b*NK + k
    const int t     = threadIdx.x;

    const float* __restrict__ src = stack ? tfRk : Rk;
    float* __restrict__ outD  = out + OFF_D + (size_t)stack * SZ_D;
    float* __restrict__ outKP = out + OFF_KP + (size_t)stack * SZ_KP;
    float* __restrict__ outZ  = out + OFF_Z + (size_t)stack * SZ_Z;

    const float4* __restrict__ in4 = (const float4*)(src + (size_t)bk * HW);
    float4* __restrict__ o4        = (float4*)(outD + (size_t)bk * HW);

    float s = 0.f, sx = 0.f, sy = 0.f;

    // element index for float4 #t is 4*t; maintain (row, col) incrementally
    // to avoid per-iteration integer div/mod. Stride per iter: 4*THREADS = 1024
    // elements = 10 rows + 64 cols (NW = 96).
    int row = (4 * t) / NW;
    int col = (4 * t) % NW;

#pragma unroll
    for (int i = 0; i < PER_T; i++) {
        const int idx = t + i * THREADS;     // float4 index within the map
        // Streaming load: bulk input is read once (except 1 elem/map in epilogue)
        float4 v = __ldcs(&in4[idx]);
        const float hh = (float)row;
        const float w0 = (float)col;

        float d0 = sigm(v.x);
        float d1 = sigm(v.y);
        float d2 = sigm(v.z);
        float d3 = sigm(v.w);
        // Streaming store: Dk output is never re-read by this kernel
        __stcs(&o4[idx], make_float4(d0, d1, d2, d3));

        const float ds = d0 + d1 + d2 + d3;
        s  += ds;
        sy += ds * hh;
        sx += d0 * w0 + d1 * (w0 + 1.f) + d2 * (w0 + 2.f) + d3 * (w0 + 3.f);

        // advance by 1024 elements: +10 rows, +64 cols (mod 96)
        row += 10;
        col += 64;
        if (col >= NW) { col -= NW; row += 1; }
    }

    // ---- block reduction of (s, sx, sy) ----
    const unsigned FULL = 0xFFFFFFFFu;
#pragma unroll
    for (int off = 16; off > 0; off >>= 1) {
        s  += __shfl_down_sync(FULL, s,  off);
        sx += __shfl_down_sync(FULL, sx, off);
        sy += __shfl_down_sync(FULL, sy, off);
    }

    __shared__ float sh_s[THREADS / 32];
    __shared__ float sh_sx[THREADS / 32];
    __shared__ float sh_sy[THREADS / 32];
    const int warp = t >> 5;
    const int lane = t & 31;
    if (lane == 0) { sh_s[warp] = s; sh_sx[warp] = sx; sh_sy[warp] = sy; }
    __syncthreads();

    if (t == 0) {
        float zeta = 0.f, kx = 0.f, ky = 0.f;
#pragma unroll
        for (int i = 0; i < THREADS / 32; i++) {
            zeta += sh_s[i];
            kx   += sh_sx[i];
            ky   += sh_sy[i];
        }

        // jnp.round = round-half-even = rintf (default RN rounding mode)
        const float kpx = rintf(__fdiv_rn(kx, zeta));
        const float kpy = rintf(__fdiv_rn(ky, zeta));
        const int wi = (int)kpx;
        const int hi = (int)kpy;

        // gather D at (hi, wi): recompute sigmoid directly from input
        const float dval = sigm(src[(size_t)bk * HW + hi * NW + wi]);

        const int b = bk >> 6;   // / NK
        const int k = bk & 63;   // % NK
        float* __restrict__ kpb = outKP + (size_t)b * (3 * NK * 2);

        // Match JAX's two-rounding mul-then-add exactly (block FFMA contraction,
        // since the result feeds trunc and a 1-ulp shift could flip a unit).
        const float px = __fmul_rn(kpx, dval);
        const float py = __fmul_rn(kpy, dval);

        // keypoint[:, 0:K]  = kp
        kpb[k * 2 + 0] = kpx;
        kpb[k * 2 + 1] = kpy;
        // keypoint[:, K:2K] = trunc(kp + kp*d)
        kpb[(NK + k) * 2 + 0] = truncf(__fadd_rn(kpx, px));
        kpb[(NK + k) * 2 + 1] = truncf(__fadd_rn(kpy, py));
        // keypoint[:, 2K:3K] = trunc(kp - kp*d)
        kpb[(2 * NK + k) * 2 + 0] = truncf(__fsub_rn(kpx, px));
        kpb[(2 * NK + k) * 2 + 1] = truncf(__fsub_rn(kpy, py));

        outZ[bk] = zeta;
    }
}

extern "C" void kernel_launch(void* const* d_in, const int* in_sizes, int n_in,
                              void* d_out, int out_size) {
    const float* Rk   = (const float*)d_in[0];
    const float* tfRk = (const float*)d_in[1];
    float* out = (float*)d_out;

    dim3 grid(NBK, 2, 1);
    decode_kernel<<<grid, THREADS>>>(Rk, tfRk, out);
}

// round 13
// speedup vs baseline: 1.0685x; 1.0685x over previous
#include <cuda_runtime.h>

// Problem constants (from reference): B=16, K=64, H=96, W=96
#define NB 16
#define NK 64
#define NH 96
#define NW 96
#define HW (NH * NW)            // 9216
#define NBK (NB * NK)           // 1024
#define THREADS 256
#define NV4 (HW / 4)            // 2304 float4 per map
#define PER_T (NV4 / THREADS)   // 9 float4 per thread

// Output segment offsets (floats), harness order:
// Dk, tf_Dk, keypoint, tf_keypoint, get_zeta, tf_get_zeta
#define OFF_D 0
#define SZ_D (NB * NK * HW)               // 9437184
#define OFF_KP (2 * SZ_D)                 // 18874368
#define SZ_KP (NB * 3 * NK * 2)           // 6144
#define OFF_Z (OFF_KP + 2 * SZ_KP)        // 18886656
#define SZ_Z (NB * NK)                    // 1024

// Precise sigmoid — used only in the 1-element/map epilogue gather.
__device__ __forceinline__ float sigm_precise(float x) {
    return 1.0f / (1.0f + expf(-x));
}

// Fast sigmoid for the bulk path: FMUL+MUFU.EX2 + MUFU.RCP+FMUL (~4 instr).
// Rel err ~1e-6 — far inside the 1e-3 tolerance for Dk, and small vs the
// existing summation-order noise on the round(kx/zeta) boundary.
__device__ __forceinline__ float sigm_fast(float x) {
    return __fdividef(1.0f, 1.0f + __expf(-x));
}

__global__ __launch_bounds__(THREADS) void decode_kernel(
    const float* __restrict__ Rk,
    const float* __restrict__ tfRk,
    float* __restrict__ out)
{
    const int stack = blockIdx.y;            // 0 = Rk, 1 = tf_Rk
    const int bk    = blockIdx.x;            // b*NK + k
    const int t     = threadIdx.x;

    const float* __restrict__ src = stack ? tfRk : Rk;
    float* __restrict__ outD  = out + OFF_D + (size_t)stack * SZ_D;
    float* __restrict__ outKP = out + OFF_KP + (size_t)stack * SZ_KP;
    float* __restrict__ outZ  = out + OFF_Z + (size_t)stack * SZ_Z;

    const float4* __restrict__ in4 = (const float4*)(src + (size_t)bk * HW);
    float4* __restrict__ o4        = (float4*)(outD + (size_t)bk * HW);

    float s = 0.f, sx = 0.f, sy = 0.f;

    // element index for float4 #t is 4*t; maintain (row, col) incrementally
    // to avoid per-iteration integer div/mod. Stride per iter: 4*THREADS = 1024
    // elements = 10 rows + 64 cols (NW = 96).
    int row = (4 * t) / NW;
    int col = (4 * t) % NW;

#pragma unroll
    for (int i = 0; i < PER_T; i++) {
        const int idx = t + i * THREADS;     // float4 index within the map
        // Streaming load: bulk input is read once (except 1 elem/map in epilogue)
        float4 v = __ldcs(&in4[idx]);
        const float hh = (float)row;
        const float w0 = (float)col;

        float d0 = sigm_fast(v.x);
        float d1 = sigm_fast(v.y);
        float d2 = sigm_fast(v.z);
        float d3 = sigm_fast(v.w);
        // Streaming store: Dk output is never re-read by this kernel
        __stcs(&o4[idx], make_float4(d0, d1, d2, d3));

        const float ds = d0 + d1 + d2 + d3;
        s  += ds;
        sy += ds * hh;
        // Σ d_i*(w0+i) = ds*w0 + (d1 + 2*d2 + 3*d3)  — 3 FFMA + 1 FADD
        float tme = fmaf(2.f, d2, d1);
        tme = fmaf(3.f, d3, tme);
        sx += fmaf(ds, w0, tme);

        // advance by 1024 elements: +10 rows, +64 cols (mod 96)
        row += 10;
        col += 64;
        if (col >= NW) { col -= NW; row += 1; }
    }

    // ---- block reduction of (s, sx, sy) ----
    const unsigned FULL = 0xFFFFFFFFu;
#pragma unroll
    for (int off = 16; off > 0; off >>= 1) {
        s  += __shfl_down_sync(FULL, s,  off);
        sx += __shfl_down_sync(FULL, sx, off);
        sy += __shfl_down_sync(FULL, sy, off);
    }

    __shared__ float sh_s[THREADS / 32];
    __shared__ float sh_sx[THREADS / 32];
    __shared__ float sh_sy[THREADS / 32];
    const int warp = t >> 5;
    const int lane = t & 31;
    if (lane == 0) { sh_s[warp] = s; sh_sx[warp] = sx; sh_sy[warp] = sy; }
    __syncthreads();

    if (t == 0) {
        float zeta = 0.f, kx = 0.f, ky = 0.f;
#pragma unroll
        for (int i = 0; i < THREADS / 32; i++) {
            zeta += sh_s[i];
            kx   += sh_sx[i];
            ky   += sh_sy[i];
        }

        // jnp.round = round-half-even = rintf (default RN rounding mode)
        const float kpx = rintf(__fdiv_rn(kx, zeta));
        const float kpy = rintf(__fdiv_rn(ky, zeta));
        const int wi = (int)kpx;
        const int hi = (int)kpy;

        // gather D at (hi, wi): precise sigmoid directly from input (matches
        // the reference gather to fp32 accuracy; 1 element per map — free)
        const float dval = sigm_precise(src[(size_t)bk * HW + hi * NW + wi]);

        const int b = bk >> 6;   // / NK
        const int k = bk & 63;   // % NK
        float* __restrict__ kpb = outKP + (size_t)b * (3 * NK * 2);

        // Match JAX's two-rounding mul-then-add exactly (block FFMA contraction,
        // since the result feeds trunc and a 1-ulp shift could flip a unit).
        const float px = __fmul_rn(kpx, dval);
        const float py = __fmul_rn(kpy, dval);

        // keypoint[:, 0:K]  = kp
        kpb[k * 2 + 0] = kpx;
        kpb[k * 2 + 1] = kpy;
        // keypoint[:, K:2K] = trunc(kp + kp*d)
        kpb[(NK + k) * 2 + 0] = truncf(__fadd_rn(kpx, px));
        kpb[(NK + k) * 2 + 1] = truncf(__fadd_rn(kpy, py));
        // keypoint[:, 2K:3K] = trunc(kp - kp*d)
        kpb[(2 * NK + k) * 2 + 0] = truncf(__fsub_rn(kpx, px));
        kpb[(2 * NK + k) * 2 + 1] = truncf(__fsub_rn(kpy, py));

        outZ[bk] = zeta;
    }
}

extern "C" void kernel_launch(void* const* d_in, const int* in_sizes, int n_in,
                              void* d_out, int out_size) {
    const float* Rk   = (const float*)d_in[0];
    const float* tfRk = (const float*)d_in[1];
    float* out = (float*)d_out;

    dim3 grid(NBK, 2, 1);
    decode_kernel<<<grid, THREADS>>>(Rk, tfRk, out);
}